// round 3
// baseline (speedup 1.0000x reference)
#include <cuda_runtime.h>
#include <math.h>

// ---------------------------------------------------------------------------
// Problem constants
// ---------------------------------------------------------------------------
#define BATCH 32
#define CIN   256
#define SIDE  64
#define NTOK  1024          // 32x32 tokens
#define KD    256           // q/k/v channels
#define SCALE 0.0625f       // 1/sqrt(256)

// GEMM tiling
#define BLK 64
#define TBK 16
#define SST 68              // smem row stride (pad) -- 68*4 bytes = 272, 16B aligned

// ---------------------------------------------------------------------------
// Scratch (device globals -- no runtime allocation allowed)
// ---------------------------------------------------------------------------
__device__ float g_pb  [3 * NTOK * KD];          // pos+bias term, [t][n][o]
__device__ float g_wt  [3 * 1024 * KD];          // transposed proj weights [t][k][o]
__device__ float g_upwt[KD * 1024];              // transposed up weights [v][j]
__device__ float g_qkv [3 * BATCH * NTOK * KD];  // Q/K/V, [t][b][n][o]
__device__ float g_S   [BATCH * NTOK * NTOK];    // scores / probs (in place)
__device__ float g_o1  [BATCH * NTOK * KD];      // attn @ V, [b][n][v]

// ---------------------------------------------------------------------------
// Positional table T[e][p]:  p<=0 -> 0 ; even e -> sin, odd e -> cos
// ---------------------------------------------------------------------------
__device__ __forceinline__ float posT(int e, int p) {
    if (p <= 0) return 0.0f;
    float inv = __powf(10000.0f, -(float)(2 * (e >> 1)) / 16.0f);
    float a = (float)p * inv;
    return (e & 1) ? cosf(a) : sinf(a);
}

// ---------------------------------------------------------------------------
// K0: per-(t,n,o) bias = conv bias + separable positional-channel contribution
// Padding-correct: a tap contributes only if BOTH row>=0 and col>=0.
//   row-dep channels: kw=0 taps vanish when ox==0 (col=-1)
//   col-dep channels: kh=0 taps vanish when oy==0 (row=-1)
// posT handles row/col <= 0 (pad -1 and zeroed pos row 0 both give 0).
// ---------------------------------------------------------------------------
__global__ void pb_kernel(const float* __restrict__ qw, const float* __restrict__ qb,
                          const float* __restrict__ kw, const float* __restrict__ kb,
                          const float* __restrict__ vw, const float* __restrict__ vb) {
    int gid = blockIdx.x * 256 + threadIdx.x;       // (t*1024 + n)*256 + o
    int o = gid & 255;
    int n = (gid >> 8) & 1023;
    int t = gid >> 18;
    const float* w  = (t == 0) ? qw : (t == 1) ? kw : vw;
    const float* bb = (t == 0) ? qb : (t == 1) ? kb : vb;
    int oy = n >> 5, ox = n & 31;
    float cx = (ox > 0) ? 1.0f : 0.0f;              // kw=0 taps valid?
    float cy = (oy > 0) ? 1.0f : 0.0f;              // kh=0 taps valid?
    float acc = bb[o];
    const float* wo = w + (size_t)o * 1152;         // 288 channels * 4
#pragma unroll
    for (int e = 0; e < 16; e++) {
        const float* wx = wo + (256 + e) * 4;       // row-dependent pos channel
        const float* wy = wo + (272 + e) * 4;       // col-dependent pos channel
        acc += (wx[0] * cx + wx[1]) * posT(e, 2 * oy - 1)
             + (wx[2] * cx + wx[3]) * posT(e, 2 * oy)
             + (wy[0] * cy + wy[2]) * posT(e, 2 * ox - 1)
             + (wy[1] * cy + wy[3]) * posT(e, 2 * ox);
    }
    g_pb[gid] = acc;
}

// ---------------------------------------------------------------------------
// K0b: transpose first-256-channel proj weights to [t][k][o]
// ---------------------------------------------------------------------------
__global__ void wt_kernel(const float* __restrict__ qw,
                          const float* __restrict__ kw,
                          const float* __restrict__ vw) {
    int gid = blockIdx.x * 256 + threadIdx.x;       // (t*1024 + k)*256 + o
    int o = gid & 255;
    int k = (gid >> 8) & 1023;
    int t = gid >> 18;
    const float* w = (t == 0) ? qw : (t == 1) ? kw : vw;
    g_wt[gid] = w[(size_t)o * 1152 + k];
}

// ---------------------------------------------------------------------------
// K0c: transpose up weights.  JAX conv_transpose(transpose_kernel=True,"IOHW")
// computes out[q] = sum_p in[p] * up_w[q][p][kh][kw]  (out channel = dim0!).
// B[v][j] with j = o*4 + kh*2 + kw  ->  g_upwt[v*1024 + j] = upw[o*1024 + v*4 + (kh*2+kw)]
// ---------------------------------------------------------------------------
__global__ void upwt_kernel(const float* __restrict__ upw) {
    int gid = blockIdx.x * 256 + threadIdx.x;       // v*1024 + j
    int j = gid & 1023;
    int v = gid >> 10;
    g_upwt[gid] = upw[(size_t)(j >> 2) * 1024 + v * 4 + (j & 3)];
}

// ---------------------------------------------------------------------------
// Shared 64x64x16 fp32 tile compute (4x4 per thread, float4 smem reads)
// ---------------------------------------------------------------------------
#define TILE_COMPUTE(As, Bs, acc, ty, tx)                                      \
    _Pragma("unroll")                                                          \
    for (int kk = 0; kk < TBK; kk++) {                                         \
        float4 a = *(const float4*)&As[kk * SST + (ty) * 4];                   \
        float4 bv = *(const float4*)&Bs[kk * SST + (tx) * 4];                  \
        acc[0][0] += a.x * bv.x; acc[0][1] += a.x * bv.y;                      \
        acc[0][2] += a.x * bv.z; acc[0][3] += a.x * bv.w;                      \
        acc[1][0] += a.y * bv.x; acc[1][1] += a.y * bv.y;                      \
        acc[1][2] += a.y * bv.z; acc[1][3] += a.y * bv.w;                      \
        acc[2][0] += a.z * bv.x; acc[2][1] += a.z * bv.y;                      \
        acc[2][2] += a.z * bv.z; acc[2][3] += a.z * bv.w;                      \
        acc[3][0] += a.w * bv.x; acc[3][1] += a.w * bv.y;                      \
        acc[3][2] += a.w * bv.z; acc[3][3] += a.w * bv.w;                      \
    }

// ---------------------------------------------------------------------------
// G1: fused im2col-gather projection GEMM  ->  Q/K/V[t][b][n][o], ReLU(conv+pb)
// ---------------------------------------------------------------------------
__global__ __launch_bounds__(256) void proj_kernel(const float* __restrict__ x) {
    int b = blockIdx.z / 3, t = blockIdx.z % 3;
    int n0 = blockIdx.x * BLK, o0 = blockIdx.y * BLK;
    int tid = threadIdx.x;
    __shared__ __align__(16) float As[TBK * SST];
    __shared__ __align__(16) float Bs[TBK * SST];

    int n_l = tid & 63;
    int kk0 = tid >> 6;                                 // 0..3
    int n = n0 + n_l, oy = n >> 5, ox = n & 31;
    const float* aptr[4];
    bool aval[4];
#pragma unroll
    for (int i = 0; i < 4; i++) {
        int kk = kk0 + 4 * i;
        int kh = (kk >> 1) & 1, kwb = kk & 1;
        int c0 = kk >> 2;
        int row = 2 * oy - 1 + kh, col = 2 * ox - 1 + kwb;
        aval[i] = (row >= 0 && col >= 0);
        int rr = aval[i] ? row : 0, cc = aval[i] ? col : 0;
        aptr[i] = x + (((size_t)b * CIN + c0) * SIDE + rr) * SIDE + cc;
    }
    const float* bptr = g_wt + ((size_t)t * 1024 + kk0) * KD + o0 + n_l;

    float acc[4][4] = {};
    int ty = tid >> 4, tx = tid & 15;

    for (int k0 = 0; k0 < 1024; k0 += TBK) {
#pragma unroll
        for (int i = 0; i < 4; i++) {
            As[(kk0 + 4 * i) * SST + n_l] = aval[i] ? aptr[i][0] : 0.0f;
            aptr[i] += 4 * SIDE * SIDE;                 // c += 4
            Bs[(kk0 + 4 * i) * SST + n_l] = bptr[i * 4 * KD];
        }
        bptr += TBK * KD;
        __syncthreads();
        TILE_COMPUTE(As, Bs, acc, ty, tx);
        __syncthreads();
    }

    const float* pbp = g_pb + (size_t)t * NTOK * KD;
    float* outp = g_qkv + ((size_t)t * BATCH + b) * NTOK * KD;
#pragma unroll
    for (int i = 0; i < 4; i++) {
        int nn = n0 + ty * 4 + i;
        float4 pv = *(const float4*)&pbp[(size_t)nn * KD + o0 + tx * 4];
        float4 r;
        r.x = fmaxf(acc[i][0] + pv.x, 0.0f);
        r.y = fmaxf(acc[i][1] + pv.y, 0.0f);
        r.z = fmaxf(acc[i][2] + pv.z, 0.0f);
        r.w = fmaxf(acc[i][3] + pv.w, 0.0f);
        *(float4*)&outp[(size_t)nn * KD + o0 + tx * 4] = r;
    }
}

// ---------------------------------------------------------------------------
// G2: scores S[n][m] = (Q[n].K[m])/16 ; only lower-triangular tiles
// ---------------------------------------------------------------------------
__global__ __launch_bounds__(256) void score_kernel() {
    int nt = blockIdx.x, mt = blockIdx.y, b = blockIdx.z;
    if (mt > nt) return;
    int n0 = nt * BLK, m0 = mt * BLK;
    const float* Q = g_qkv + (size_t)b * NTOK * KD;
    const float* Km = g_qkv + ((size_t)BATCH + b) * NTOK * KD;
    int tid = threadIdx.x;
    __shared__ __align__(16) float As[TBK * SST];
    __shared__ __align__(16) float Bs[TBK * SST];

    int kkA = tid & 15, rA = tid >> 4;
    float acc[4][4] = {};
    int ty = tid >> 4, tx = tid & 15;

    for (int k0 = 0; k0 < KD; k0 += TBK) {
#pragma unroll
        for (int i = 0; i < 4; i++) {
            As[kkA * SST + rA + 16 * i] = Q [(size_t)(n0 + rA + 16 * i) * KD + k0 + kkA];
            Bs[kkA * SST + rA + 16 * i] = Km[(size_t)(m0 + rA + 16 * i) * KD + k0 + kkA];
        }
        __syncthreads();
        TILE_COMPUTE(As, Bs, acc, ty, tx);
        __syncthreads();
    }

    float* Sp = g_S + (size_t)b * NTOK * NTOK;
#pragma unroll
    for (int i = 0; i < 4; i++) {
        int nn = n0 + ty * 4 + i;
        float4 r;
        r.x = acc[i][0] * SCALE; r.y = acc[i][1] * SCALE;
        r.z = acc[i][2] * SCALE; r.w = acc[i][3] * SCALE;
        *(float4*)&Sp[(size_t)nn * NTOK + m0 + tx * 4] = r;
    }
}

// ---------------------------------------------------------------------------
// Softmax, in place. Row n: valid m in [0, n]; zeros for [n+1, Lpad).
// ---------------------------------------------------------------------------
__global__ __launch_bounds__(128) void softmax_kernel() {
    int bid = blockIdx.x;
    int n = bid & 1023;
    float* row = g_S + (size_t)bid * NTOK;
    int L = n + 1;
    int Lpad = ((n >> 6) + 1) << 6;
    __shared__ float buf[1024];
    __shared__ float red[4];
    int tid = threadIdx.x;

    float mx = -1e30f;
    for (int m = tid; m < L; m += 128) { float v = row[m]; buf[m] = v; mx = fmaxf(mx, v); }
#pragma unroll
    for (int off = 16; off; off >>= 1) mx = fmaxf(mx, __shfl_xor_sync(~0u, mx, off));
    if ((tid & 31) == 0) red[tid >> 5] = mx;
    __syncthreads();
    mx = fmaxf(fmaxf(red[0], red[1]), fmaxf(red[2], red[3]));

    float s = 0.0f;
    for (int m = tid; m < L; m += 128) { float e = __expf(buf[m] - mx); buf[m] = e; s += e; }
#pragma unroll
    for (int off = 16; off; off >>= 1) s += __shfl_xor_sync(~0u, s, off);
    __syncthreads();
    if ((tid & 31) == 0) red[tid >> 5] = s;
    __syncthreads();
    s = red[0] + red[1] + red[2] + red[3];
    float inv = 1.0f / s;

    for (int m = tid; m < Lpad; m += 128) row[m] = (m < L) ? buf[m] * inv : 0.0f;
}

// ---------------------------------------------------------------------------
// G3: out1[n][v] = sum_m attn[n][m] * V[m][v]  (triangular k loop)
// ---------------------------------------------------------------------------
__global__ __launch_bounds__(256) void av_kernel() {
    int nt = blockIdx.x, vt = blockIdx.y, b = blockIdx.z;
    int n0 = nt * BLK, v0 = vt * BLK;
    const float* A = g_S + (size_t)b * NTOK * NTOK;
    const float* V = g_qkv + ((size_t)2 * BATCH + b) * NTOK * KD;
    int tid = threadIdx.x;
    __shared__ __align__(16) float As[TBK * SST];
    __shared__ __align__(16) float Bs[TBK * SST];

    int kkA = tid & 15, rA = tid >> 4;
    int vB  = tid & 63, kkB = tid >> 6;
    float acc[4][4] = {};
    int ty = tid >> 4, tx = tid & 15;
    int kmax = (nt + 1) * BLK;

    for (int k0 = 0; k0 < kmax; k0 += TBK) {
#pragma unroll
        for (int i = 0; i < 4; i++) {
            As[kkA * SST + rA + 16 * i] = A[(size_t)(n0 + rA + 16 * i) * NTOK + k0 + kkA];
            Bs[(kkB + 4 * i) * SST + vB] = V[(size_t)(k0 + kkB + 4 * i) * KD + v0 + vB];
        }
        __syncthreads();
        TILE_COMPUTE(As, Bs, acc, ty, tx);
        __syncthreads();
    }

    float* Op = g_o1 + (size_t)b * NTOK * KD;
#pragma unroll
    for (int i = 0; i < 4; i++) {
        int nn = n0 + ty * 4 + i;
        float4 r;
        r.x = acc[i][0]; r.y = acc[i][1]; r.z = acc[i][2]; r.w = acc[i][3];
        *(float4*)&Op[(size_t)nn * KD + v0 + tx * 4] = r;
    }
}

// ---------------------------------------------------------------------------
// G4: convTranspose GEMM  C[n][j] = sum_v out1[n][v] * upwt[v][j],
//     j = o*4 + kh*2 + kw.  Fused scatter epilogue: out = x + up_b + C.
// ---------------------------------------------------------------------------
__global__ __launch_bounds__(256) void up_kernel(const float* __restrict__ xin,
                                                 const float* __restrict__ upb,
                                                 float* __restrict__ out) {
    int nt = blockIdx.x, jt = blockIdx.y, b = blockIdx.z;
    int n0 = nt * BLK, j0 = jt * BLK;
    const float* A = g_o1 + (size_t)b * NTOK * KD;
    int tid = threadIdx.x;
    __shared__ __align__(16) float As[TBK * SST];
    __shared__ __align__(16) float Bs[TBK * SST];
    __shared__ float Cs[BLK * 65];

    int kkA = tid & 15, rA = tid >> 4;
    int jB  = tid & 63, kkB = tid >> 6;
    float acc[4][4] = {};
    int ty = tid >> 4, tx = tid & 15;

    for (int k0 = 0; k0 < KD; k0 += TBK) {
#pragma unroll
        for (int i = 0; i < 4; i++) {
            As[kkA * SST + rA + 16 * i] = A[(size_t)(n0 + rA + 16 * i) * KD + k0 + kkA];
            Bs[(kkB + 4 * i) * SST + jB] = g_upwt[(size_t)(k0 + kkB + 4 * i) * 1024 + j0 + jB];
        }
        __syncthreads();
        TILE_COMPUTE(As, Bs, acc, ty, tx);
        __syncthreads();
    }

#pragma unroll
    for (int i = 0; i < 4; i++)
#pragma unroll
        for (int j = 0; j < 4; j++)
            Cs[(ty * 4 + i) * 65 + tx * 4 + j] = acc[i][j];
    __syncthreads();

    int o_base = jt * 16;
    int r0 = nt * 4;
#pragma unroll
    for (int it = 0; it < 16; it++) {
        int e = it * 256 + tid;
        int c   = e & 63;
        int r_l = (e >> 6) & 3;
        int o_l = e >> 8;
        int jl = o_l * 4 + (r_l & 1) * 2 + (c & 1);
        int nl = (r_l >> 1) * 32 + (c >> 1);
        int o = o_base + o_l;
        size_t gi = (((size_t)b * CIN + o) * SIDE + r0 + r_l) * SIDE + c;
        out[gi] = xin[gi] + upb[o] + Cs[nl * 65 + jl];
    }
}

// ---------------------------------------------------------------------------
// Launch
// ---------------------------------------------------------------------------
extern "C" void kernel_launch(void* const* d_in, const int* in_sizes, int n_in,
                              void* d_out, int out_size) {
    const float* x   = (const float*)d_in[0];
    const float* q_w = (const float*)d_in[1];
    const float* q_b = (const float*)d_in[2];
    const float* k_w = (const float*)d_in[3];
    const float* k_b = (const float*)d_in[4];
    const float* v_w = (const float*)d_in[5];
    const float* v_b = (const float*)d_in[6];
    const float* up_w = (const float*)d_in[7];
    const float* up_b = (const float*)d_in[8];
    float* out = (float*)d_out;

    pb_kernel<<<3 * NTOK * KD / 256, 256>>>(q_w, q_b, k_w, k_b, v_w, v_b);
    wt_kernel<<<3 * 1024 * KD / 256, 256>>>(q_w, k_w, v_w);
    upwt_kernel<<<KD * 1024 / 256, 256>>>(up_w);
    proj_kernel<<<dim3(16, 4, BATCH * 3), 256>>>(x);
    score_kernel<<<dim3(16, 16, BATCH), 256>>>();
    softmax_kernel<<<BATCH * NTOK, 128>>>();
    av_kernel<<<dim3(16, 4, BATCH), 256>>>();
    up_kernel<<<dim3(16, 16, BATCH), 256>>>(x, up_b, out);
}

// round 4
// speedup vs baseline: 1.1893x; 1.1893x over previous
#include <cuda_runtime.h>
#include <math.h>

// ---------------------------------------------------------------------------
// Problem constants
// ---------------------------------------------------------------------------
#define BATCH 32
#define CIN   256
#define SIDE  64
#define NTOK  1024          // 32x32 tokens
#define KD    256           // q/k/v channels
#define SCALE 0.0625f       // 1/sqrt(256)

// GEMM tiling: 128x128 block, BK=16, 256 threads, 8x8 microtile
#define BM   128
#define BN   128
#define BKK  16
#define ASTR 132            // smem row stride (floats); 132*4=528 bytes, 16B multiple

// ---------------------------------------------------------------------------
// Scratch (device globals -- no runtime allocation allowed)
// ---------------------------------------------------------------------------
__device__ float g_pb  [3 * NTOK * KD];          // pos+bias term, [t][n][o]
__device__ float g_wt  [3 * 1024 * KD];          // transposed proj weights [t][k][o]
__device__ float g_upwt[KD * 1024];              // transposed up weights [v][j]
__device__ float g_qkv [3 * BATCH * NTOK * KD];  // Q/K/V, [t][b][n][o]
__device__ float g_S   [BATCH * NTOK * NTOK];    // scores / probs (in place)
__device__ float g_o1  [BATCH * NTOK * KD];      // attn @ V, [b][n][v]

// ---------------------------------------------------------------------------
// Positional table
// ---------------------------------------------------------------------------
__device__ __forceinline__ float posT(int e, int p) {
    if (p <= 0) return 0.0f;
    float inv = __powf(10000.0f, -(float)(2 * (e >> 1)) / 16.0f);
    float a = (float)p * inv;
    return (e & 1) ? cosf(a) : sinf(a);
}

// ---------------------------------------------------------------------------
// K0: per-(t,n,o) bias = conv bias + separable positional contribution
// (padding-correct cross terms)
// ---------------------------------------------------------------------------
__global__ void pb_kernel(const float* __restrict__ qw, const float* __restrict__ qb,
                          const float* __restrict__ kw, const float* __restrict__ kb,
                          const float* __restrict__ vw, const float* __restrict__ vb) {
    int gid = blockIdx.x * 256 + threadIdx.x;
    int o = gid & 255;
    int n = (gid >> 8) & 1023;
    int t = gid >> 18;
    const float* w  = (t == 0) ? qw : (t == 1) ? kw : vw;
    const float* bb = (t == 0) ? qb : (t == 1) ? kb : vb;
    int oy = n >> 5, ox = n & 31;
    float cx = (ox > 0) ? 1.0f : 0.0f;
    float cy = (oy > 0) ? 1.0f : 0.0f;
    float acc = bb[o];
    const float* wo = w + (size_t)o * 1152;
#pragma unroll
    for (int e = 0; e < 16; e++) {
        const float* wx = wo + (256 + e) * 4;
        const float* wy = wo + (272 + e) * 4;
        acc += (wx[0] * cx + wx[1]) * posT(e, 2 * oy - 1)
             + (wx[2] * cx + wx[3]) * posT(e, 2 * oy)
             + (wy[0] * cy + wy[2]) * posT(e, 2 * ox - 1)
             + (wy[1] * cy + wy[3]) * posT(e, 2 * ox);
    }
    g_pb[gid] = acc;
}

__global__ void wt_kernel(const float* __restrict__ qw,
                          const float* __restrict__ kw,
                          const float* __restrict__ vw) {
    int gid = blockIdx.x * 256 + threadIdx.x;
    int o = gid & 255;
    int k = (gid >> 8) & 1023;
    int t = gid >> 18;
    const float* w = (t == 0) ? qw : (t == 1) ? kw : vw;
    g_wt[gid] = w[(size_t)o * 1152 + k];
}

// upwt[v][j] = upw[o][v][kh][kw], j = o*4 + kh*2 + kw (JAX transpose_kernel)
__global__ void upwt_kernel(const float* __restrict__ upw) {
    int gid = blockIdx.x * 256 + threadIdx.x;
    int j = gid & 1023;
    int v = gid >> 10;
    g_upwt[gid] = upw[(size_t)(j >> 2) * 1024 + v * 4 + (j & 3)];
}

// ---------------------------------------------------------------------------
// 8x8 microtile inner product over one BKK slab
// ---------------------------------------------------------------------------
#define FRAG_COMPUTE(As, Bs, acc, ty, tx)                                      \
    _Pragma("unroll")                                                          \
    for (int kk = 0; kk < BKK; kk++) {                                         \
        float4 a0 = *(const float4*)&(As)[kk * ASTR + (ty) * 4];               \
        float4 a1 = *(const float4*)&(As)[kk * ASTR + 64 + (ty) * 4];          \
        float4 b0 = *(const float4*)&(Bs)[kk * ASTR + (tx) * 4];               \
        float4 b1 = *(const float4*)&(Bs)[kk * ASTR + 64 + (tx) * 4];          \
        float ar_[8] = {a0.x, a0.y, a0.z, a0.w, a1.x, a1.y, a1.z, a1.w};       \
        float br_[8] = {b0.x, b0.y, b0.z, b0.w, b1.x, b1.y, b1.z, b1.w};       \
        _Pragma("unroll")                                                      \
        for (int ii = 0; ii < 8; ii++)                                         \
            _Pragma("unroll")                                                  \
            for (int jj = 0; jj < 8; jj++)                                     \
                acc[ii][jj] += ar_[ii] * br_[jj];                              \
    }

// Transposed A slab load: src points at A[row0][k0], lda = row stride.
// Produces As[kk][row] for kk in [0,16), row in [0,128).
#define LOAD_T(As, src, lda)                                                   \
    do {                                                                       \
        _Pragma("unroll")                                                      \
        for (int h_ = 0; h_ < 2; h_++) {                                       \
            int id_ = (int)threadIdx.x + 256 * h_;                             \
            int row_ = id_ >> 2;                                               \
            int c4_ = (id_ & 3) * 4;                                           \
            float4 v_ = *(const float4*)((src) + (size_t)row_ * (lda) + c4_);  \
            (As)[(c4_ + 0) * ASTR + row_] = v_.x;                              \
            (As)[(c4_ + 1) * ASTR + row_] = v_.y;                              \
            (As)[(c4_ + 2) * ASTR + row_] = v_.z;                              \
            (As)[(c4_ + 3) * ASTR + row_] = v_.w;                              \
        }                                                                      \
    } while (0)

// Direct B slab load: src points at B[k0][col0], ldb = row stride.
#define LOAD_B(Bs, src, ldb)                                                   \
    do {                                                                       \
        int bl_ = (int)threadIdx.x & 127;                                      \
        int kb_ = (int)threadIdx.x >> 7;                                       \
        _Pragma("unroll")                                                      \
        for (int i_ = 0; i_ < 8; i_++)                                         \
            (Bs)[(kb_ * 8 + i_) * ASTR + bl_] =                                \
                (src)[(size_t)(kb_ * 8 + i_) * (ldb) + bl_];                   \
    } while (0)

// ---------------------------------------------------------------------------
// G1: fused im2col projection GEMM -> ReLU(conv + pb) into g_qkv
// grid: (8 n-tiles, 2 o-tiles, b*3+t)
// ---------------------------------------------------------------------------
__global__ __launch_bounds__(256, 2) void proj_kernel(const float* __restrict__ x) {
    int b = blockIdx.z / 3, t = blockIdx.z % 3;
    int n0 = blockIdx.x * BM, o0 = blockIdx.y * BN;
    int tid = threadIdx.x;
    __shared__ __align__(16) float As[BKK * ASTR];
    __shared__ __align__(16) float Bs[BKK * ASTR];
    int ty = tid >> 4, tx = tid & 15;

    // A gather: As[kk][n_l], k = c*4 + kh*2 + kw
    int n_l = tid & 127;
    int kk2 = tid >> 7;                         // 0/1 -> kk = kk2*8 + i
    int n = n0 + n_l, oy = n >> 5, ox = n & 31;
    const float* aptr[8];
    bool aval[8];
#pragma unroll
    for (int i = 0; i < 8; i++) {
        int kk = kk2 * 8 + i;
        int c_l = kk >> 2, kh = (kk >> 1) & 1, kwb = kk & 1;
        int row = 2 * oy - 1 + kh, col = 2 * ox - 1 + kwb;
        aval[i] = (row >= 0 && col >= 0);
        int rr = aval[i] ? row : 0, cc = aval[i] ? col : 0;
        aptr[i] = x + (((size_t)b * CIN + c_l) * SIDE + rr) * SIDE + cc;
    }
    const float* bptr = g_wt + ((size_t)t * 1024 + kk2 * 8) * KD + o0 + n_l;

    float acc[8][8] = {};
    for (int k0 = 0; k0 < 1024; k0 += BKK) {
#pragma unroll
        for (int i = 0; i < 8; i++) {
            As[(kk2 * 8 + i) * ASTR + n_l] = aval[i] ? aptr[i][0] : 0.0f;
            aptr[i] += 4 * SIDE * SIDE;         // channel += 4
            Bs[(kk2 * 8 + i) * ASTR + n_l] = bptr[(size_t)i * KD];
        }
        bptr += (size_t)BKK * KD;
        __syncthreads();
        FRAG_COMPUTE(As, Bs, acc, ty, tx);
        __syncthreads();
    }

    const float* pbp = g_pb + (size_t)t * NTOK * KD;
    float* outp = g_qkv + ((size_t)t * BATCH + b) * NTOK * KD;
#pragma unroll
    for (int i0 = 0; i0 < 2; i0++)
#pragma unroll
        for (int i = 0; i < 4; i++) {
            int nn = n0 + i0 * 64 + ty * 4 + i;
#pragma unroll
            for (int j0 = 0; j0 < 2; j0++) {
                int cc = o0 + j0 * 64 + tx * 4;
                float4 pv = *(const float4*)&pbp[(size_t)nn * KD + cc];
                float4 r;
                r.x = fmaxf(acc[i0 * 4 + i][j0 * 4 + 0] + pv.x, 0.0f);
                r.y = fmaxf(acc[i0 * 4 + i][j0 * 4 + 1] + pv.y, 0.0f);
                r.z = fmaxf(acc[i0 * 4 + i][j0 * 4 + 2] + pv.z, 0.0f);
                r.w = fmaxf(acc[i0 * 4 + i][j0 * 4 + 3] + pv.w, 0.0f);
                *(float4*)&outp[(size_t)nn * KD + cc] = r;
            }
        }
}

// ---------------------------------------------------------------------------
// G2: S[n][m] = (Q[n].K[m])/16, lower-triangular 128-tiles only
// grid: (8 nt, 8 mt, 32 b)
// ---------------------------------------------------------------------------
__global__ __launch_bounds__(256, 2) void score_kernel() {
    int nt = blockIdx.x, mt = blockIdx.y, b = blockIdx.z;
    if (mt > nt) return;
    const float* Q  = g_qkv + (size_t)b * NTOK * KD + (size_t)nt * BM * KD;
    const float* Km = g_qkv + ((size_t)BATCH + b) * NTOK * KD + (size_t)mt * BN * KD;
    __shared__ __align__(16) float As[BKK * ASTR];
    __shared__ __align__(16) float Bs[BKK * ASTR];
    int tid = threadIdx.x, ty = tid >> 4, tx = tid & 15;

    float acc[8][8] = {};
    for (int k0 = 0; k0 < KD; k0 += BKK) {
        LOAD_T(As, Q + k0, KD);
        LOAD_T(Bs, Km + k0, KD);
        __syncthreads();
        FRAG_COMPUTE(As, Bs, acc, ty, tx);
        __syncthreads();
    }

    float* Sp = g_S + (size_t)b * NTOK * NTOK;
    int n0 = nt * BM, m0 = mt * BN;
#pragma unroll
    for (int i0 = 0; i0 < 2; i0++)
#pragma unroll
        for (int i = 0; i < 4; i++) {
            int nn = n0 + i0 * 64 + ty * 4 + i;
#pragma unroll
            for (int j0 = 0; j0 < 2; j0++) {
                int mm = m0 + j0 * 64 + tx * 4;
                float4 r;
                r.x = acc[i0 * 4 + i][j0 * 4 + 0] * SCALE;
                r.y = acc[i0 * 4 + i][j0 * 4 + 1] * SCALE;
                r.z = acc[i0 * 4 + i][j0 * 4 + 2] * SCALE;
                r.w = acc[i0 * 4 + i][j0 * 4 + 3] * SCALE;
                *(float4*)&Sp[(size_t)nn * NTOK + mm] = r;
            }
        }
}

// ---------------------------------------------------------------------------
// Softmax, in place. Zeros out to 128-aligned pad (av tiles read that far).
// ---------------------------------------------------------------------------
__global__ __launch_bounds__(128) void softmax_kernel() {
    int bid = blockIdx.x;
    int n = bid & 1023;
    float* row = g_S + (size_t)bid * NTOK;
    int L = n + 1;
    int Lpad = ((n >> 7) + 1) << 7;
    __shared__ float buf[1024];
    __shared__ float red[4];
    int tid = threadIdx.x;

    float mx = -1e30f;
    for (int m = tid; m < L; m += 128) { float v = row[m]; buf[m] = v; mx = fmaxf(mx, v); }
#pragma unroll
    for (int off = 16; off; off >>= 1) mx = fmaxf(mx, __shfl_xor_sync(~0u, mx, off));
    if ((tid & 31) == 0) red[tid >> 5] = mx;
    __syncthreads();
    mx = fmaxf(fmaxf(red[0], red[1]), fmaxf(red[2], red[3]));

    float s = 0.0f;
    for (int m = tid; m < L; m += 128) { float e = __expf(buf[m] - mx); buf[m] = e; s += e; }
#pragma unroll
    for (int off = 16; off; off >>= 1) s += __shfl_xor_sync(~0u, s, off);
    __syncthreads();
    if ((tid & 31) == 0) red[tid >> 5] = s;
    __syncthreads();
    s = red[0] + red[1] + red[2] + red[3];
    float inv = 1.0f / s;

    for (int m = tid; m < Lpad; m += 128) row[m] = (m < L) ? buf[m] * inv : 0.0f;
}

// ---------------------------------------------------------------------------
// G3: out1[n][v] = sum_m attn[n][m] * V[m][v], triangular k loop
// grid: (8 nt, 2 vt, 32 b)
// ---------------------------------------------------------------------------
__global__ __launch_bounds__(256, 2) void av_kernel() {
    int nt = blockIdx.x, vt = blockIdx.y, b = blockIdx.z;
    const float* A = g_S + (size_t)b * NTOK * NTOK + (size_t)nt * BM * NTOK;
    const float* V = g_qkv + ((size_t)2 * BATCH + b) * NTOK * KD;
    __shared__ __align__(16) float As[BKK * ASTR];
    __shared__ __align__(16) float Bs[BKK * ASTR];
    int tid = threadIdx.x, ty = tid >> 4, tx = tid & 15;
    int v0 = vt * BN;
    int kmax = (nt + 1) * BM;

    float acc[8][8] = {};
    for (int k0 = 0; k0 < kmax; k0 += BKK) {
        LOAD_T(As, A + k0, NTOK);
        LOAD_B(Bs, V + (size_t)k0 * KD + v0, KD);
        __syncthreads();
        FRAG_COMPUTE(As, Bs, acc, ty, tx);
        __syncthreads();
    }

    float* Op = g_o1 + (size_t)b * NTOK * KD;
    int n0 = nt * BM;
#pragma unroll
    for (int i0 = 0; i0 < 2; i0++)
#pragma unroll
        for (int i = 0; i < 4; i++) {
            int nn = n0 + i0 * 64 + ty * 4 + i;
#pragma unroll
            for (int j0 = 0; j0 < 2; j0++) {
                int cc = v0 + j0 * 64 + tx * 4;
                float4 r;
                r.x = acc[i0 * 4 + i][j0 * 4 + 0];
                r.y = acc[i0 * 4 + i][j0 * 4 + 1];
                r.z = acc[i0 * 4 + i][j0 * 4 + 2];
                r.w = acc[i0 * 4 + i][j0 * 4 + 3];
                *(float4*)&Op[(size_t)nn * KD + cc] = r;
            }
        }
}

// ---------------------------------------------------------------------------
// G4: convT GEMM C[n][j] = sum_v o1[n][v]*upwt[v][j], fused residual scatter.
// grid: (8 nt, 8 jt, 32 b). Epilogue stages 64-row halves in smem, then
// coalesced scatter over out[b][jt*32..+32][nt*8+i0*4..+4][0..64].
// ---------------------------------------------------------------------------
__global__ __launch_bounds__(256, 2) void up_kernel(const float* __restrict__ xin,
                                                    const float* __restrict__ upb,
                                                    float* __restrict__ out) {
    int nt = blockIdx.x, jt = blockIdx.y, b = blockIdx.z;
    int n0 = nt * BM, j0 = jt * BN;
    const float* A = g_o1 + (size_t)b * NTOK * KD + (size_t)n0 * KD;
    __shared__ __align__(16) union {
        float ab[2 * BKK * ASTR];
        float cs[64 * 132];
    } sm;
    float* As = sm.ab;
    float* Bs = sm.ab + BKK * ASTR;
    float* Cs = sm.cs;
    int tid = threadIdx.x, ty = tid >> 4, tx = tid & 15;

    float acc[8][8] = {};
    for (int k0 = 0; k0 < KD; k0 += BKK) {
        LOAD_T(As, A + k0, KD);
        LOAD_B(Bs, g_upwt + (size_t)k0 * 1024 + j0, 1024);
        __syncthreads();
        FRAG_COMPUTE(As, Bs, acc, ty, tx);
        __syncthreads();
    }

#pragma unroll
    for (int i0 = 0; i0 < 2; i0++) {
        __syncthreads();
#pragma unroll
        for (int i = 0; i < 4; i++) {
            int rl = ty * 4 + i;
            float4 r0v, r1v;
            r0v.x = acc[i0 * 4 + i][0]; r0v.y = acc[i0 * 4 + i][1];
            r0v.z = acc[i0 * 4 + i][2]; r0v.w = acc[i0 * 4 + i][3];
            r1v.x = acc[i0 * 4 + i][4]; r1v.y = acc[i0 * 4 + i][5];
            r1v.z = acc[i0 * 4 + i][6]; r1v.w = acc[i0 * 4 + i][7];
            *(float4*)&Cs[rl * 132 + tx * 4] = r0v;
            *(float4*)&Cs[rl * 132 + 64 + tx * 4] = r1v;
        }
        __syncthreads();

        int r0 = nt * 8 + i0 * 4;                       // output row base (4 rows)
#pragma unroll
        for (int it = 0; it < 32; it++) {
            int e = it * 256 + tid;
            int c   = e & 63;
            int r_l = (e >> 6) & 3;
            int o_l = e >> 8;                           // 0..31
            int jl = o_l * 4 + (r_l & 1) * 2 + (c & 1);
            int nl = (r_l >> 1) * 32 + (c >> 1);
            int o = jt * 32 + o_l;
            size_t gi = (((size_t)b * CIN + o) * SIDE + r0 + r_l) * SIDE + c;
            out[gi] = xin[gi] + upb[o] + Cs[nl * 132 + jl];
        }
    }
}

// ---------------------------------------------------------------------------
// Launch
// ---------------------------------------------------------------------------
extern "C" void kernel_launch(void* const* d_in, const int* in_sizes, int n_in,
                              void* d_out, int out_size) {
    const float* x   = (const float*)d_in[0];
    const float* q_w = (const float*)d_in[1];
    const float* q_b = (const float*)d_in[2];
    const float* k_w = (const float*)d_in[3];
    const float* k_b = (const float*)d_in[4];
    const float* v_w = (const float*)d_in[5];
    const float* v_b = (const float*)d_in[6];
    const float* up_w = (const float*)d_in[7];
    const float* up_b = (const float*)d_in[8];
    float* out = (float*)d_out;

    pb_kernel<<<3 * NTOK * KD / 256, 256>>>(q_w, q_b, k_w, k_b, v_w, v_b);
    wt_kernel<<<3 * 1024 * KD / 256, 256>>>(q_w, k_w, v_w);
    upwt_kernel<<<KD * 1024 / 256, 256>>>(up_w);
    proj_kernel<<<dim3(8, 2, BATCH * 3), 256>>>(x);
    score_kernel<<<dim3(8, 8, BATCH), 256>>>();
    softmax_kernel<<<BATCH * NTOK, 128>>>();
    av_kernel<<<dim3(8, 2, BATCH), 256>>>();
    up_kernel<<<dim3(8, 8, BATCH), 256>>>(x, up_b, out);
}

// round 5
// speedup vs baseline: 1.5279x; 1.2847x over previous
#include <cuda_runtime.h>
#include <math.h>

// ---------------------------------------------------------------------------
// Problem constants
// ---------------------------------------------------------------------------
#define BATCH 32
#define CIN   256
#define SIDE  64
#define NTOK  1024
#define KD    256
#define SCALE 0.0625f

// GEMM tiling: 128x128 block, BK=32, 256 threads (8 warps, 2x4), warp 64x32
#define BM  128
#define BN  128
#define BK  32
#define SKP 36              // smem row stride in floats (conflict-free frags)
#define SMEM_FLOATS (4 * 128 * SKP)   // two ping-pong (As,Bs) pairs
#define SMEM_BYTES  (SMEM_FLOATS * 4) // 73728

// ---------------------------------------------------------------------------
// Scratch
// ---------------------------------------------------------------------------
__device__ float g_pb  [3 * NTOK * KD];           // pos+bias [t][n][o]
__device__ float g_wt  [3 * KD * 1024];           // proj weights [t][o][k]
__device__ float g_upwt[1024 * KD];               // up weights [j][v]
__device__ float g_qkv [3 * BATCH * NTOK * KD];   // Q/K/V [t][b][n][o]
__device__ float g_vt  [BATCH * KD * NTOK];       // V transposed [b][v][m]
__device__ float g_S   [BATCH * NTOK * NTOK];     // scores / probs
__device__ float g_o1  [BATCH * NTOK * KD];       // attn @ V [b][n][v]

// ---------------------------------------------------------------------------
// Helpers
// ---------------------------------------------------------------------------
__device__ __forceinline__ unsigned f2tf(float f) {
    unsigned u;
    asm("cvt.rna.tf32.f32 %0, %1;" : "=r"(u) : "f"(f));
    return u;
}

__device__ __forceinline__ float posT(int e, int p) {
    if (p <= 0) return 0.0f;
    float inv = __powf(10000.0f, -(float)(2 * (e >> 1)) / 16.0f);
    float a = (float)p * inv;
    return (e & 1) ? cosf(a) : sinf(a);
}

// ---------------------------------------------------------------------------
// Preprocessing kernels
// ---------------------------------------------------------------------------
__global__ void pb_kernel(const float* __restrict__ qw, const float* __restrict__ qb,
                          const float* __restrict__ kw, const float* __restrict__ kb,
                          const float* __restrict__ vw, const float* __restrict__ vb) {
    int gid = blockIdx.x * 256 + threadIdx.x;
    int o = gid & 255;
    int n = (gid >> 8) & 1023;
    int t = gid >> 18;
    const float* w  = (t == 0) ? qw : (t == 1) ? kw : vw;
    const float* bb = (t == 0) ? qb : (t == 1) ? kb : vb;
    int oy = n >> 5, ox = n & 31;
    float cx = (ox > 0) ? 1.0f : 0.0f;
    float cy = (oy > 0) ? 1.0f : 0.0f;
    float acc = bb[o];
    const float* wo = w + (size_t)o * 1152;
#pragma unroll
    for (int e = 0; e < 16; e++) {
        const float* wx = wo + (256 + e) * 4;
        const float* wy = wo + (272 + e) * 4;
        acc += (wx[0] * cx + wx[1]) * posT(e, 2 * oy - 1)
             + (wx[2] * cx + wx[3]) * posT(e, 2 * oy)
             + (wy[0] * cy + wy[2]) * posT(e, 2 * ox - 1)
             + (wy[1] * cy + wy[3]) * posT(e, 2 * ox);
    }
    g_pb[gid] = acc;
}

// g_wt[t][o][k] = w[o][k] (first 1024 of 1152 per o)
__global__ void wt_kernel(const float* __restrict__ qw,
                          const float* __restrict__ kw,
                          const float* __restrict__ vw) {
    int gid = blockIdx.x * 256 + threadIdx.x;     // (t*256 + o)*1024 + k
    int k = gid & 1023;
    int o = (gid >> 10) & 255;
    int t = gid >> 18;
    const float* w = (t == 0) ? qw : (t == 1) ? kw : vw;
    g_wt[gid] = w[(size_t)o * 1152 + k];
}

// g_upwt[j][v] = upw[o=j>>2][v][tap=j&3]  (JAX transpose_kernel: out ch = dim0)
__global__ void upwt_kernel(const float* __restrict__ upw) {
    int gid = blockIdx.x * 256 + threadIdx.x;     // j*256 + v
    int v = gid & 255;
    int j = gid >> 8;
    g_upwt[gid] = upw[(size_t)(j >> 2) * 1024 + v * 4 + (j & 3)];
}

// g_vt[b][v][m] = V[b][m][v]
__global__ void vt_kernel() {
    __shared__ float tile[32][33];
    int b = blockIdx.z;
    int m0 = blockIdx.x * 32, v0 = blockIdx.y * 32;
    const float* V = g_qkv + ((size_t)2 * BATCH + b) * NTOK * KD;
    float* Vt = g_vt + (size_t)b * KD * NTOK;
    int tx = threadIdx.x, ty = threadIdx.y;
#pragma unroll
    for (int i = 0; i < 32; i += 8)
        tile[ty + i][tx] = V[(size_t)(m0 + ty + i) * KD + v0 + tx];
    __syncthreads();
#pragma unroll
    for (int i = 0; i < 32; i += 8)
        Vt[(size_t)(v0 + ty + i) * NTOK + m0 + tx] = tile[tx][ty + i];
}

// ---------------------------------------------------------------------------
// Row staging: 128 rows x 32 k, float4 global -> tf32 -> float4 smem
// ---------------------------------------------------------------------------
#define STAGE_ROWS(dst, src, ld)                                               \
    do {                                                                       \
        _Pragma("unroll")                                                      \
        for (int i_ = 0; i_ < 4; i_++) {                                       \
            int f4_ = (int)threadIdx.x + 256 * i_;                             \
            int r_ = f4_ >> 3;                                                 \
            int c_ = (f4_ & 7) * 4;                                            \
            float4 v_ = *(const float4*)((src) + (size_t)r_ * (ld) + c_);      \
            float4 w_;                                                         \
            w_.x = __uint_as_float(f2tf(v_.x));                                \
            w_.y = __uint_as_float(f2tf(v_.y));                                \
            w_.z = __uint_as_float(f2tf(v_.z));                                \
            w_.w = __uint_as_float(f2tf(v_.w));                                \
            *(float4*)&(dst)[r_ * SKP + c_] = w_;                              \
        }                                                                      \
    } while (0)

// ---------------------------------------------------------------------------
// Warp-tile mma over one BK=32 slab: warp computes 64x32 (4 m-frags x 4 n-frags)
// ---------------------------------------------------------------------------
__device__ __forceinline__ void mma_slab(const float* As, const float* Bs,
                                         float acc[4][4][4],
                                         int m_off, int n_off, int qid, int tig) {
#pragma unroll
    for (int k8 = 0; k8 < 4; k8++) {
        int k0 = k8 * 8;
        unsigned a[4][4], bfr[4][2];
#pragma unroll
        for (int mf = 0; mf < 4; mf++) {
            int r = m_off + mf * 16 + qid;
            a[mf][0] = __float_as_uint(As[r * SKP + k0 + tig]);
            a[mf][1] = __float_as_uint(As[(r + 8) * SKP + k0 + tig]);
            a[mf][2] = __float_as_uint(As[r * SKP + k0 + tig + 4]);
            a[mf][3] = __float_as_uint(As[(r + 8) * SKP + k0 + tig + 4]);
        }
#pragma unroll
        for (int nf = 0; nf < 4; nf++) {
            int c = n_off + nf * 8 + qid;
            bfr[nf][0] = __float_as_uint(Bs[c * SKP + k0 + tig]);
            bfr[nf][1] = __float_as_uint(Bs[c * SKP + k0 + tig + 4]);
        }
#pragma unroll
        for (int mf = 0; mf < 4; mf++)
#pragma unroll
            for (int nf = 0; nf < 4; nf++)
                asm volatile(
                    "mma.sync.aligned.m16n8k8.row.col.f32.tf32.tf32.f32 "
                    "{%0,%1,%2,%3}, {%4,%5,%6,%7}, {%8,%9}, {%0,%1,%2,%3};"
                    : "+f"(acc[mf][nf][0]), "+f"(acc[mf][nf][1]),
                      "+f"(acc[mf][nf][2]), "+f"(acc[mf][nf][3])
                    : "r"(a[mf][0]), "r"(a[mf][1]), "r"(a[mf][2]), "r"(a[mf][3]),
                      "r"(bfr[nf][0]), "r"(bfr[nf][1]));
    }
}

#define GEMM_PREAMBLE()                                                        \
    extern __shared__ float sm[];                                              \
    float* Abuf[2] = {sm, sm + 2 * 128 * SKP};                                 \
    float* Bbuf[2] = {sm + 128 * SKP, sm + 3 * 128 * SKP};                     \
    int tid = threadIdx.x;                                                     \
    int lane = tid & 31, wid = tid >> 5;                                       \
    int qid = lane >> 2, tig = lane & 3;                                       \
    int m_off = (wid >> 2) * 64, n_off = (wid & 3) * 32;                       \
    float acc[4][4][4] = {};

// ---------------------------------------------------------------------------
// G1: projection GEMM (im2col gather A, weight B), ReLU(acc+pb) -> g_qkv
// grid: (8 nt, 2 ot, 3*B)
// ---------------------------------------------------------------------------
__global__ __launch_bounds__(256) void proj_kernel(const float* __restrict__ x) {
    GEMM_PREAMBLE();
    int b = blockIdx.z / 3, t = blockIdx.z % 3;
    int n0 = blockIdx.x * BM, o0 = blockIdx.y * BN;

    // A gather setup: thread owns token n_l, channel slots c_l = (tid>>7)+2i
    int n_l = tid & 127;
    int ch0 = tid >> 7;                          // 0/1
    int n = n0 + n_l, oy = n >> 5, ox = n & 31;
    bool vy = oy > 0, vx = ox > 0;
    const float* basep = x + ((size_t)(b * CIN + ch0) * SIDE + (2 * oy - 1)) * SIDE
                           + (2 * ox - 1);
    int sbase = n_l * SKP + ch0 * 4;             // smem float index for i=0

#define PROJ_STAGE_A(dst, s)                                                   \
    do {                                                                       \
        _Pragma("unroll")                                                      \
        for (int i_ = 0; i_ < 4; i_++) {                                       \
            const float* p_ = basep + ((size_t)(s) * 8 + 2 * i_) * (SIDE * SIDE); \
            float v00 = (vy && vx) ? p_[0] : 0.0f;                             \
            float v01 = vy ? p_[1] : 0.0f;                                     \
            float v10 = vx ? p_[SIDE] : 0.0f;                                  \
            float v11 = p_[SIDE + 1];                                          \
            float4 w_;                                                         \
            w_.x = __uint_as_float(f2tf(v00));                                 \
            w_.y = __uint_as_float(f2tf(v01));                                 \
            w_.z = __uint_as_float(f2tf(v10));                                 \
            w_.w = __uint_as_float(f2tf(v11));                                 \
            *(float4*)&(dst)[sbase + i_ * 8] = w_;                             \
        }                                                                      \
    } while (0)

    const float* Wb = g_wt + (size_t)(t * 256 + o0) * 1024;

    PROJ_STAGE_A(Abuf[0], 0);
    STAGE_ROWS(Bbuf[0], Wb, 1024);
    __syncthreads();

    for (int s = 0; s < 32; s++) {
        int p = s & 1;
        if (s + 1 < 32) {
            PROJ_STAGE_A(Abuf[1 - p], s + 1);
            STAGE_ROWS(Bbuf[1 - p], Wb + (s + 1) * 32, 1024);
        }
        mma_slab(Abuf[p], Bbuf[p], acc, m_off, n_off, qid, tig);
        __syncthreads();
    }

    const float* pbp = g_pb + (size_t)t * NTOK * KD;
    float* outp = g_qkv + ((size_t)t * BATCH + b) * NTOK * KD;
#pragma unroll
    for (int mf = 0; mf < 4; mf++)
#pragma unroll
        for (int nf = 0; nf < 4; nf++) {
            int r = n0 + m_off + mf * 16 + qid;
            int c = o0 + n_off + nf * 8 + 2 * tig;
            float2 p0 = *(const float2*)&pbp[(size_t)r * KD + c];
            float2 p1 = *(const float2*)&pbp[(size_t)(r + 8) * KD + c];
            float2 r0, r1;
            r0.x = fmaxf(acc[mf][nf][0] + p0.x, 0.0f);
            r0.y = fmaxf(acc[mf][nf][1] + p0.y, 0.0f);
            r1.x = fmaxf(acc[mf][nf][2] + p1.x, 0.0f);
            r1.y = fmaxf(acc[mf][nf][3] + p1.y, 0.0f);
            *(float2*)&outp[(size_t)r * KD + c] = r0;
            *(float2*)&outp[(size_t)(r + 8) * KD + c] = r1;
        }
}

// ---------------------------------------------------------------------------
// G2: scores, lower-triangular tiles. grid (8 nt, 8 mt, B)
// ---------------------------------------------------------------------------
__global__ __launch_bounds__(256) void score_kernel() {
    int nt = blockIdx.x, mt = blockIdx.y, b = blockIdx.z;
    if (mt > nt) return;
    GEMM_PREAMBLE();
    const float* Q  = g_qkv + (size_t)b * NTOK * KD + (size_t)nt * BM * KD;
    const float* Km = g_qkv + ((size_t)BATCH + b) * NTOK * KD + (size_t)mt * BN * KD;

    STAGE_ROWS(Abuf[0], Q, KD);
    STAGE_ROWS(Bbuf[0], Km, KD);
    __syncthreads();
    for (int s = 0; s < 8; s++) {
        int p = s & 1;
        if (s + 1 < 8) {
            STAGE_ROWS(Abuf[1 - p], Q + (s + 1) * 32, KD);
            STAGE_ROWS(Bbuf[1 - p], Km + (s + 1) * 32, KD);
        }
        mma_slab(Abuf[p], Bbuf[p], acc, m_off, n_off, qid, tig);
        __syncthreads();
    }

    float* Sp = g_S + (size_t)b * NTOK * NTOK;
    int n0 = nt * BM, m0 = mt * BN;
#pragma unroll
    for (int mf = 0; mf < 4; mf++)
#pragma unroll
        for (int nf = 0; nf < 4; nf++) {
            int r = n0 + m_off + mf * 16 + qid;
            int c = m0 + n_off + nf * 8 + 2 * tig;
            float2 r0, r1;
            r0.x = acc[mf][nf][0] * SCALE; r0.y = acc[mf][nf][1] * SCALE;
            r1.x = acc[mf][nf][2] * SCALE; r1.y = acc[mf][nf][3] * SCALE;
            *(float2*)&Sp[(size_t)r * NTOK + c] = r0;
            *(float2*)&Sp[(size_t)(r + 8) * NTOK + c] = r1;
        }
}

// ---------------------------------------------------------------------------
// Softmax, in place; zero-pads row to 128-aligned length
// ---------------------------------------------------------------------------
__global__ __launch_bounds__(128) void softmax_kernel() {
    int bid = blockIdx.x;
    int n = bid & 1023;
    float* row = g_S + (size_t)bid * NTOK;
    int L = n + 1;
    int Lpad = ((n >> 7) + 1) << 7;
    __shared__ float buf[1024];
    __shared__ float red[4];
    int tid = threadIdx.x;

    float mx = -1e30f;
    for (int m = tid; m < L; m += 128) { float v = row[m]; buf[m] = v; mx = fmaxf(mx, v); }
#pragma unroll
    for (int off = 16; off; off >>= 1) mx = fmaxf(mx, __shfl_xor_sync(~0u, mx, off));
    if ((tid & 31) == 0) red[tid >> 5] = mx;
    __syncthreads();
    mx = fmaxf(fmaxf(red[0], red[1]), fmaxf(red[2], red[3]));

    float s = 0.0f;
    for (int m = tid; m < L; m += 128) { float e = __expf(buf[m] - mx); buf[m] = e; s += e; }
#pragma unroll
    for (int off = 16; off; off >>= 1) s += __shfl_xor_sync(~0u, s, off);
    __syncthreads();
    if ((tid & 31) == 0) red[tid >> 5] = s;
    __syncthreads();
    s = red[0] + red[1] + red[2] + red[3];
    float inv = 1.0f / s;

    for (int m = tid; m < Lpad; m += 128) row[m] = (m < L) ? buf[m] * inv : 0.0f;
}

// ---------------------------------------------------------------------------
// G3: out1 = probs @ V (B = V^T rows), triangular k. grid (8 nt, 2 vt, B)
// ---------------------------------------------------------------------------
__global__ __launch_bounds__(256) void av_kernel() {
    GEMM_PREAMBLE();
    int nt = blockIdx.x, vt = blockIdx.y, b = blockIdx.z;
    const float* P  = g_S + (size_t)b * NTOK * NTOK + (size_t)nt * BM * NTOK;
    const float* Vt = g_vt + (size_t)b * KD * NTOK + (size_t)vt * BN * NTOK;
    int ns = (nt + 1) * 4;

    STAGE_ROWS(Abuf[0], P, NTOK);
    STAGE_ROWS(Bbuf[0], Vt, NTOK);
    __syncthreads();
    for (int s = 0; s < ns; s++) {
        int p = s & 1;
        if (s + 1 < ns) {
            STAGE_ROWS(Abuf[1 - p], P + (s + 1) * 32, NTOK);
            STAGE_ROWS(Bbuf[1 - p], Vt + (s + 1) * 32, NTOK);
        }
        mma_slab(Abuf[p], Bbuf[p], acc, m_off, n_off, qid, tig);
        __syncthreads();
    }

    float* Op = g_o1 + (size_t)b * NTOK * KD;
    int n0 = nt * BM, v0 = vt * BN;
#pragma unroll
    for (int mf = 0; mf < 4; mf++)
#pragma unroll
        for (int nf = 0; nf < 4; nf++) {
            int r = n0 + m_off + mf * 16 + qid;
            int c = v0 + n_off + nf * 8 + 2 * tig;
            *(float2*)&Op[(size_t)r * KD + c] = make_float2(acc[mf][nf][0], acc[mf][nf][1]);
            *(float2*)&Op[(size_t)(r + 8) * KD + c] = make_float2(acc[mf][nf][2], acc[mf][nf][3]);
        }
}

// ---------------------------------------------------------------------------
// G4: convT GEMM (A=o1, B=upwt[j][v]) + fused residual scatter
// grid (8 nt, 8 jt, B)
// ---------------------------------------------------------------------------
__global__ __launch_bounds__(256) void up_kernel(const float* __restrict__ xin,
                                                 const float* __restrict__ upb,
                                                 float* __restrict__ out) {
    GEMM_PREAMBLE();
    int nt = blockIdx.x, jt = blockIdx.y, b = blockIdx.z;
    int n0 = nt * BM, j0 = jt * BN;
    const float* A = g_o1 + (size_t)b * NTOK * KD + (size_t)n0 * KD;
    const float* Bw = g_upwt + (size_t)j0 * KD;

    STAGE_ROWS(Abuf[0], A, KD);
    STAGE_ROWS(Bbuf[0], Bw, KD);
    __syncthreads();
    for (int s = 0; s < 8; s++) {
        int p = s & 1;
        if (s + 1 < 8) {
            STAGE_ROWS(Abuf[1 - p], A + (s + 1) * 32, KD);
            STAGE_ROWS(Bbuf[1 - p], Bw + (s + 1) * 32, KD);
        }
        mma_slab(Abuf[p], Bbuf[p], acc, m_off, n_off, qid, tig);
        __syncthreads();
    }

    // stage C tile (128 n x 128 j) into smem, then coalesced scatter
    float* Cs = sm;                               // reuse; 128*130 floats
#pragma unroll
    for (int mf = 0; mf < 4; mf++)
#pragma unroll
        for (int nf = 0; nf < 4; nf++) {
            int rl = m_off + mf * 16 + qid;
            int cl = n_off + nf * 8 + 2 * tig;
            *(float2*)&Cs[rl * 130 + cl] = make_float2(acc[mf][nf][0], acc[mf][nf][1]);
            *(float2*)&Cs[(rl + 8) * 130 + cl] = make_float2(acc[mf][nf][2], acc[mf][nf][3]);
        }
    __syncthreads();

    // tile covers out[b][jt*32 .. +32][nt*8 .. +8][0..64]
#pragma unroll
    for (int it = 0; it < 64; it++) {
        int e = it * 256 + tid;
        int c   = e & 63;
        int r_l = (e >> 6) & 7;
        int o_l = e >> 9;                         // 0..31
        int jl = o_l * 4 + (r_l & 1) * 2 + (c & 1);
        int nl = (r_l >> 1) * 32 + (c >> 1);
        int o = jt * 32 + o_l;
        size_t gi = (((size_t)b * CIN + o) * SIDE + nt * 8 + r_l) * SIDE + c;
        out[gi] = xin[gi] + upb[o] + Cs[nl * 130 + jl];
    }
}

// ---------------------------------------------------------------------------
// Launch
// ---------------------------------------------------------------------------
extern "C" void kernel_launch(void* const* d_in, const int* in_sizes, int n_in,
                              void* d_out, int out_size) {
    const float* x   = (const float*)d_in[0];
    const float* q_w = (const float*)d_in[1];
    const float* q_b = (const float*)d_in[2];
    const float* k_w = (const float*)d_in[3];
    const float* k_b = (const float*)d_in[4];
    const float* v_w = (const float*)d_in[5];
    const float* v_b = (const float*)d_in[6];
    const float* up_w = (const float*)d_in[7];
    const float* up_b = (const float*)d_in[8];
    float* out = (float*)d_out;

    static bool attr_done = false;
    if (!attr_done) {
        cudaFuncSetAttribute(proj_kernel,  cudaFuncAttributeMaxDynamicSharedMemorySize, SMEM_BYTES);
        cudaFuncSetAttribute(score_kernel, cudaFuncAttributeMaxDynamicSharedMemorySize, SMEM_BYTES);
        cudaFuncSetAttribute(av_kernel,    cudaFuncAttributeMaxDynamicSharedMemorySize, SMEM_BYTES);
        cudaFuncSetAttribute(up_kernel,    cudaFuncAttributeMaxDynamicSharedMemorySize, SMEM_BYTES);
        attr_done = true;
    }

    pb_kernel<<<3 * NTOK * KD / 256, 256>>>(q_w, q_b, k_w, k_b, v_w, v_b);
    wt_kernel<<<3 * 256 * 1024 / 256, 256>>>(q_w, k_w, v_w);
    upwt_kernel<<<1024 * KD / 256, 256>>>(up_w);
    proj_kernel<<<dim3(8, 2, BATCH * 3), 256, SMEM_BYTES>>>(x);
    vt_kernel<<<dim3(32, 8, BATCH), dim3(32, 8)>>>();
    score_kernel<<<dim3(8, 8, BATCH), 256, SMEM_BYTES>>>();
    softmax_kernel<<<BATCH * NTOK, 128>>>();
    av_kernel<<<dim3(8, 2, BATCH), 256, SMEM_BYTES>>>();
    up_kernel<<<dim3(8, 8, BATCH), 256, SMEM_BYTES>>>(x, up_b, out);
}

// round 7
// speedup vs baseline: 2.1107x; 1.3815x over previous
#include <cuda_runtime.h>
#include <math.h>

// ---------------------------------------------------------------------------
// Problem constants
// ---------------------------------------------------------------------------
#define BATCH 32
#define CIN   256
#define SIDE  64
#define NTOK  1024
#define KD    256
#define SCALE 0.0625f

// GEMM tiling: 128x128 block, BK=32, 256 threads (8 warps 2x4), warp 64x32
#define BM  128
#define BN  128
#define BK  32
#define SKP 36
#define SMEM_FLOATS (4 * 128 * SKP)
#define SMEM_BYTES  (SMEM_FLOATS * 4)   // 73728

#define XP 66                            // padded side
#define XPC (XP * XP)                    // floats per padded channel

// ---------------------------------------------------------------------------
// Scratch  (all mma-input buffers hold tf32-rounded values)
// ---------------------------------------------------------------------------
__device__ float g_pb  [3 * NTOK * KD];           // pos+bias [t][n][o] (fp32)
__device__ float g_wt  [3 * KD * 1024];           // proj weights [t][o][k] (tf32)
__device__ float g_upwt[1024 * KD];               // up weights [j][v] (tf32)
__device__ float g_xp  [BATCH * CIN * XPC];       // zero-padded x (tf32)
__device__ float g_qkv [3 * BATCH * NTOK * KD];   // Q/K/V [t][b][n][o] (tf32)
__device__ float g_vt  [BATCH * KD * NTOK];       // V transposed (tf32)
__device__ float g_S   [BATCH * NTOK * NTOK];     // scores fp32 / probs tf32
__device__ float g_o1  [BATCH * NTOK * KD];       // attn @ V (tf32)

// ---------------------------------------------------------------------------
// Helpers
// ---------------------------------------------------------------------------
__device__ __forceinline__ float f2tf(float f) {
    unsigned u;
    asm("cvt.rna.tf32.f32 %0, %1;" : "=r"(u) : "f"(f));
    return __uint_as_float(u);
}

__device__ __forceinline__ void cp16(unsigned d, const void* s) {
    asm volatile("cp.async.cg.shared.global [%0], [%1], 16;\n" :: "r"(d), "l"(s));
}
__device__ __forceinline__ void cp8(unsigned d, const void* s) {
    asm volatile("cp.async.ca.shared.global [%0], [%1], 8;\n" :: "r"(d), "l"(s));
}
#define CP_COMMIT() asm volatile("cp.async.commit_group;\n" ::: "memory")
#define CP_WAIT1()  asm volatile("cp.async.wait_group 1;\n" ::: "memory")
#define CP_WAIT0()  asm volatile("cp.async.wait_group 0;\n" ::: "memory")

__device__ __forceinline__ float posT(int e, int p) {
    if (p <= 0) return 0.0f;
    float inv = __powf(10000.0f, -(float)(2 * (e >> 1)) / 16.0f);
    float a = (float)p * inv;
    return (e & 1) ? cosf(a) : sinf(a);
}

// ---------------------------------------------------------------------------
// Preprocessing
// ---------------------------------------------------------------------------
__global__ void pb_kernel(const float* __restrict__ qw, const float* __restrict__ qb,
                          const float* __restrict__ kw, const float* __restrict__ kb,
                          const float* __restrict__ vw, const float* __restrict__ vb) {
    int gid = blockIdx.x * 256 + threadIdx.x;
    int o = gid & 255;
    int n = (gid >> 8) & 1023;
    int t = gid >> 18;
    const float* w  = (t == 0) ? qw : (t == 1) ? kw : vw;
    const float* bb = (t == 0) ? qb : (t == 1) ? kb : vb;
    int oy = n >> 5, ox = n & 31;
    float cx = (ox > 0) ? 1.0f : 0.0f;
    float cy = (oy > 0) ? 1.0f : 0.0f;
    float acc = bb[o];
    const float* wo = w + (size_t)o * 1152;
#pragma unroll
    for (int e = 0; e < 16; e++) {
        const float* wx = wo + (256 + e) * 4;
        const float* wy = wo + (272 + e) * 4;
        acc += (wx[0] * cx + wx[1]) * posT(e, 2 * oy - 1)
             + (wx[2] * cx + wx[3]) * posT(e, 2 * oy)
             + (wy[0] * cy + wy[2]) * posT(e, 2 * ox - 1)
             + (wy[1] * cy + wy[3]) * posT(e, 2 * ox);
    }
    g_pb[gid] = acc;
}

__global__ void wt_kernel(const float* __restrict__ qw,
                          const float* __restrict__ kw,
                          const float* __restrict__ vw) {
    int gid = blockIdx.x * 256 + threadIdx.x;     // (t*256 + o)*1024 + k
    int k = gid & 1023;
    int o = (gid >> 10) & 255;
    int t = gid >> 18;
    const float* w = (t == 0) ? qw : (t == 1) ? kw : vw;
    g_wt[gid] = f2tf(w[(size_t)o * 1152 + k]);
}

__global__ void upwt_kernel(const float* __restrict__ upw) {
    int gid = blockIdx.x * 256 + threadIdx.x;     // j*256 + v
    int v = gid & 255;
    int j = gid >> 8;
    g_upwt[gid] = f2tf(upw[(size_t)(j >> 2) * 1024 + v * 4 + (j & 3)]);
}

// zero-padded input: g_xp[b][c][rp][cp], rp=row+1, cp=col+1  (tf32-rounded)
__global__ void xpad_kernel(const float* __restrict__ x) {
    long long gid = (long long)blockIdx.x * 256 + threadIdx.x;
    if (gid >= (long long)BATCH * CIN * XPC) return;
    int cp = gid % XP;
    int rp = (gid / XP) % XP;
    long long bc = gid / XPC;
    float v = 0.0f;
    if (rp >= 1 && rp <= SIDE && cp >= 1 && cp <= SIDE)
        v = x[bc * (SIDE * SIDE) + (size_t)(rp - 1) * SIDE + (cp - 1)];
    g_xp[gid] = f2tf(v);
}

// g_vt[b][v][m] = V[b][m][v]  (V already tf32-rounded)
__global__ void vt_kernel() {
    __shared__ float tile[32][33];
    int b = blockIdx.z;
    int m0 = blockIdx.x * 32, v0 = blockIdx.y * 32;
    const float* V = g_qkv + ((size_t)2 * BATCH + b) * NTOK * KD;
    float* Vt = g_vt + (size_t)b * KD * NTOK;
    int tx = threadIdx.x, ty = threadIdx.y;
#pragma unroll
    for (int i = 0; i < 32; i += 8)
        tile[ty + i][tx] = V[(size_t)(m0 + ty + i) * KD + v0 + tx];
    __syncthreads();
#pragma unroll
    for (int i = 0; i < 32; i += 8)
        Vt[(size_t)(v0 + ty + i) * NTOK + m0 + tx] = tile[tx][ty + i];
}

// ---------------------------------------------------------------------------
// Async row staging: 128 rows x 32 k
// ---------------------------------------------------------------------------
__device__ __forceinline__ void stage_rows(float* dst, const float* src, int ld, int tid) {
#pragma unroll
    for (int i = 0; i < 4; i++) {
        int f4 = tid + 256 * i;
        int r = f4 >> 3, c = (f4 & 7) * 4;
        unsigned d = (unsigned)__cvta_generic_to_shared(dst + r * SKP + c);
        cp16(d, src + (size_t)r * ld + c);
    }
}

// ---------------------------------------------------------------------------
// Warp mma over one BK=32 slab (warp tile 64x32)
// ---------------------------------------------------------------------------
__device__ __forceinline__ void mma_slab(const float* As, const float* Bs,
                                         float acc[4][4][4],
                                         int m_off, int n_off, int qid, int tig) {
#pragma unroll
    for (int k8 = 0; k8 < 4; k8++) {
        int k0 = k8 * 8;
        unsigned a[4][4], bfr[4][2];
#pragma unroll
        for (int mf = 0; mf < 4; mf++) {
            int r = m_off + mf * 16 + qid;
            a[mf][0] = __float_as_uint(As[r * SKP + k0 + tig]);
            a[mf][1] = __float_as_uint(As[(r + 8) * SKP + k0 + tig]);
            a[mf][2] = __float_as_uint(As[r * SKP + k0 + tig + 4]);
            a[mf][3] = __float_as_uint(As[(r + 8) * SKP + k0 + tig + 4]);
        }
#pragma unroll
        for (int nf = 0; nf < 4; nf++) {
            int c = n_off + nf * 8 + qid;
            bfr[nf][0] = __float_as_uint(Bs[c * SKP + k0 + tig]);
            bfr[nf][1] = __float_as_uint(Bs[c * SKP + k0 + tig + 4]);
        }
#pragma unroll
        for (int mf = 0; mf < 4; mf++)
#pragma unroll
            for (int nf = 0; nf < 4; nf++)
                asm volatile(
                    "mma.sync.aligned.m16n8k8.row.col.f32.tf32.tf32.f32 "
                    "{%0,%1,%2,%3}, {%4,%5,%6,%7}, {%8,%9}, {%0,%1,%2,%3};"
                    : "+f"(acc[mf][nf][0]), "+f"(acc[mf][nf][1]),
                      "+f"(acc[mf][nf][2]), "+f"(acc[mf][nf][3])
                    : "r"(a[mf][0]), "r"(a[mf][1]), "r"(a[mf][2]), "r"(a[mf][3]),
                      "r"(bfr[nf][0]), "r"(bfr[nf][1]));
    }
}

#define GEMM_PREAMBLE()                                                        \
    extern __shared__ float sm[];                                              \
    float* Abuf[2] = {sm, sm + 2 * 128 * SKP};                                 \
    float* Bbuf[2] = {sm + 128 * SKP, sm + 3 * 128 * SKP};                     \
    int tid = threadIdx.x;                                                     \
    int lane = tid & 31, wid = tid >> 5;                                       \
    int qid = lane >> 2, tig = lane & 3;                                       \
    int m_off = (wid >> 2) * 64, n_off = (wid & 3) * 32;                       \
    float acc[4][4][4] = {};

#define PIPE_LOOP(NS, STAGE_S)                                                 \
    STAGE_S(0, 0);                                                             \
    CP_COMMIT();                                                               \
    for (int s = 0; s < (NS); s++) {                                           \
        int p = s & 1;                                                         \
        if (s + 1 < (NS)) {                                                    \
            STAGE_S(1 - p, s + 1);                                             \
            CP_COMMIT();                                                       \
            CP_WAIT1();                                                        \
        } else {                                                               \
            CP_WAIT0();                                                        \
        }                                                                      \
        __syncthreads();                                                       \
        mma_slab(Abuf[p], Bbuf[p], acc, m_off, n_off, qid, tig);               \
        __syncthreads();                                                       \
    }

// ---------------------------------------------------------------------------
// G1: projection GEMM, ReLU(acc+pb) -> g_qkv (tf32-rounded store)
// grid: (8 nt, 2 ot, 3*B)
// ---------------------------------------------------------------------------
__global__ __launch_bounds__(256) void proj_kernel() {
    GEMM_PREAMBLE();
    int b = blockIdx.z / 3, t = blockIdx.z % 3;
    int n0 = blockIdx.x * BM, o0 = blockIdx.y * BN;

    int n_l = tid & 127;
    int ch0 = tid >> 7;
    int n = n0 + n_l, oy = n >> 5, ox = n & 31;
    const float* xpb = g_xp + ((size_t)(b * CIN + ch0) * XP + 2 * oy) * XP + 2 * ox;
    unsigned sA[2];
    sA[0] = (unsigned)__cvta_generic_to_shared(Abuf[0] + n_l * SKP + ch0 * 4);
    sA[1] = (unsigned)__cvta_generic_to_shared(Abuf[1] + n_l * SKP + ch0 * 4);
    const float* Wb = g_wt + (size_t)(t * 256 + o0) * 1024;

#define PROJ_STAGE(bi, s)                                                      \
    do {                                                                       \
        _Pragma("unroll")                                                      \
        for (int i_ = 0; i_ < 4; i_++) {                                       \
            const float* p_ = xpb + (size_t)(8 * (s) + 2 * i_) * XPC;          \
            unsigned d_ = sA[bi] + (unsigned)(i_ * 8) * 4;                     \
            cp8(d_, p_);                                                       \
            cp8(d_ + 8, p_ + XP);                                              \
        }                                                                      \
        stage_rows(Bbuf[bi], Wb + (s) * 32, 1024, tid);                        \
    } while (0)

    PIPE_LOOP(32, PROJ_STAGE);

    const float* pbp = g_pb + (size_t)t * NTOK * KD;
    float* outp = g_qkv + ((size_t)t * BATCH + b) * NTOK * KD;
#pragma unroll
    for (int mf = 0; mf < 4; mf++)
#pragma unroll
        for (int nf = 0; nf < 4; nf++) {
            int r = n0 + m_off + mf * 16 + qid;
            int c = o0 + n_off + nf * 8 + 2 * tig;
            float2 p0 = *(const float2*)&pbp[(size_t)r * KD + c];
            float2 p1 = *(const float2*)&pbp[(size_t)(r + 8) * KD + c];
            float2 r0, r1;
            r0.x = f2tf(fmaxf(acc[mf][nf][0] + p0.x, 0.0f));
            r0.y = f2tf(fmaxf(acc[mf][nf][1] + p0.y, 0.0f));
            r1.x = f2tf(fmaxf(acc[mf][nf][2] + p1.x, 0.0f));
            r1.y = f2tf(fmaxf(acc[mf][nf][3] + p1.y, 0.0f));
            *(float2*)&outp[(size_t)r * KD + c] = r0;
            *(float2*)&outp[(size_t)(r + 8) * KD + c] = r1;
        }
}

// ---------------------------------------------------------------------------
// G2: scores, lower-triangular tiles. grid (8 nt, 8 mt, B)
// ---------------------------------------------------------------------------
__global__ __launch_bounds__(256) void score_kernel() {
    int nt = blockIdx.x, mt = blockIdx.y, b = blockIdx.z;
    if (mt > nt) return;
    GEMM_PREAMBLE();
    const float* Q  = g_qkv + (size_t)b * NTOK * KD + (size_t)nt * BM * KD;
    const float* Km = g_qkv + ((size_t)BATCH + b) * NTOK * KD + (size_t)mt * BN * KD;

#define SCORE_STAGE(bi, s)                                                     \
    do {                                                                       \
        stage_rows(Abuf[bi], Q + (s) * 32, KD, tid);                           \
        stage_rows(Bbuf[bi], Km + (s) * 32, KD, tid);                          \
    } while (0)

    PIPE_LOOP(8, SCORE_STAGE);

    float* Sp = g_S + (size_t)b * NTOK * NTOK;
    int n0 = nt * BM, m0 = mt * BN;
#pragma unroll
    for (int mf = 0; mf < 4; mf++)
#pragma unroll
        for (int nf = 0; nf < 4; nf++) {
            int r = n0 + m_off + mf * 16 + qid;
            int c = m0 + n_off + nf * 8 + 2 * tig;
            float2 r0, r1;
            r0.x = acc[mf][nf][0] * SCALE; r0.y = acc[mf][nf][1] * SCALE;
            r1.x = acc[mf][nf][2] * SCALE; r1.y = acc[mf][nf][3] * SCALE;
            *(float2*)&Sp[(size_t)r * NTOK + c] = r0;
            *(float2*)&Sp[(size_t)(r + 8) * NTOK + c] = r1;
        }
}

// ---------------------------------------------------------------------------
// Softmax; writes tf32-rounded probs (they feed the AV mma)
// ---------------------------------------------------------------------------
__global__ __launch_bounds__(128) void softmax_kernel() {
    int bid = blockIdx.x;
    int n = bid & 1023;
    float* row = g_S + (size_t)bid * NTOK;
    int L = n + 1;
    int Lpad = ((n >> 7) + 1) << 7;
    __shared__ float buf[1024];
    __shared__ float red[4];
    int tid = threadIdx.x;

    float mx = -1e30f;
    for (int m = tid; m < L; m += 128) { float v = row[m]; buf[m] = v; mx = fmaxf(mx, v); }
#pragma unroll
    for (int off = 16; off; off >>= 1) mx = fmaxf(mx, __shfl_xor_sync(~0u, mx, off));
    if ((tid & 31) == 0) red[tid >> 5] = mx;
    __syncthreads();
    mx = fmaxf(fmaxf(red[0], red[1]), fmaxf(red[2], red[3]));

    float s = 0.0f;
    for (int m = tid; m < L; m += 128) { float e = __expf(buf[m] - mx); buf[m] = e; s += e; }
#pragma unroll
    for (int off = 16; off; off >>= 1) s += __shfl_xor_sync(~0u, s, off);
    __syncthreads();
    if ((tid & 31) == 0) red[tid >> 5] = s;
    __syncthreads();
    s = red[0] + red[1] + red[2] + red[3];
    float inv = 1.0f / s;

    for (int m = tid; m < Lpad; m += 128)
        row[m] = (m < L) ? f2tf(buf[m] * inv) : 0.0f;
}

// ---------------------------------------------------------------------------
// G3: out1 = probs @ V. grid (8 nt, 2 vt, B)
// ---------------------------------------------------------------------------
__global__ __launch_bounds__(256) void av_kernel() {
    GEMM_PREAMBLE();
    int nt = blockIdx.x, vt = blockIdx.y, b = blockIdx.z;
    const float* P  = g_S + (size_t)b * NTOK * NTOK + (size_t)nt * BM * NTOK;
    const float* Vt = g_vt + (size_t)b * KD * NTOK + (size_t)vt * BN * NTOK;
    int ns = (nt + 1) * 4;

#define AV_STAGE(bi, s)                                                        \
    do {                                                                       \
        stage_rows(Abuf[bi], P + (s) * 32, NTOK, tid);                         \
        stage_rows(Bbuf[bi], Vt + (s) * 32, NTOK, tid);                        \
    } while (0)

    PIPE_LOOP(ns, AV_STAGE);

    float* Op = g_o1 + (size_t)b * NTOK * KD;
    int n0 = nt * BM, v0 = vt * BN;
#pragma unroll
    for (int mf = 0; mf < 4; mf++)
#pragma unroll
        for (int nf = 0; nf < 4; nf++) {
            int r = n0 + m_off + mf * 16 + qid;
            int c = v0 + n_off + nf * 8 + 2 * tig;
            float2 r0 = make_float2(f2tf(acc[mf][nf][0]), f2tf(acc[mf][nf][1]));
            float2 r1 = make_float2(f2tf(acc[mf][nf][2]), f2tf(acc[mf][nf][3]));
            *(float2*)&Op[(size_t)r * KD + c] = r0;
            *(float2*)&Op[(size_t)(r + 8) * KD + c] = r1;
        }
}

// ---------------------------------------------------------------------------
// G4: convT GEMM + fused residual scatter. grid (8 nt, 8 jt, B)
// ---------------------------------------------------------------------------
__global__ __launch_bounds__(256) void up_kernel(const float* __restrict__ xin,
                                                 const float* __restrict__ upb,
                                                 float* __restrict__ out) {
    GEMM_PREAMBLE();
    int nt = blockIdx.x, jt = blockIdx.y, b = blockIdx.z;
    int n0 = nt * BM, j0 = jt * BN;
    const float* A = g_o1 + (size_t)b * NTOK * KD + (size_t)n0 * KD;
    const float* Bw = g_upwt + (size_t)j0 * KD;

#define UP_STAGE(bi, s)                                                        \
    do {                                                                       \
        stage_rows(Abuf[bi], A + (s) * 32, KD, tid);                           \
        stage_rows(Bbuf[bi], Bw + (s) * 32, KD, tid);                          \
    } while (0)

    PIPE_LOOP(8, UP_STAGE);

    float* Cs = sm;                               // 128*130 floats
#pragma unroll
    for (int mf = 0; mf < 4; mf++)
#pragma unroll
        for (int nf = 0; nf < 4; nf++) {
            int rl = m_off + mf * 16 + qid;
            int cl = n_off + nf * 8 + 2 * tig;
            *(float2*)&Cs[rl * 130 + cl] = make_float2(acc[mf][nf][0], acc[mf][nf][1]);
            *(float2*)&Cs[(rl + 8) * 130 + cl] = make_float2(acc[mf][nf][2], acc[mf][nf][3]);
        }
    __syncthreads();

#pragma unroll
    for (int it = 0; it < 64; it++) {
        int e = it * 256 + tid;
        int c   = e & 63;
        int r_l = (e >> 6) & 7;
        int o_l = e >> 9;
        int jl = o_l * 4 + (r_l & 1) * 2 + (c & 1);
        int nl = (r_l >> 1) * 32 + (c >> 1);
        int o = jt * 32 + o_l;
        size_t gi = (((size_t)b * CIN + o) * SIDE + nt * 8 + r_l) * SIDE + c;
        out[gi] = xin[gi] + upb[o] + Cs[nl * 130 + jl];
    }
}

// ---------------------------------------------------------------------------
// Launch
// ---------------------------------------------------------------------------
extern "C" void kernel_launch(void* const* d_in, const int* in_sizes, int n_in,
                              void* d_out, int out_size) {
    const float* x   = (const float*)d_in[0];
    const float* q_w = (const float*)d_in[1];
    const float* q_b = (const float*)d_in[2];
    const float* k_w = (const float*)d_in[3];
    const float* k_b = (const float*)d_in[4];
    const float* v_w = (const float*)d_in[5];
    const float* v_b = (const float*)d_in[6];
    const float* up_w = (const float*)d_in[7];
    const float* up_b = (const float*)d_in[8];
    float* out = (float*)d_out;

    static bool attr_done = false;
    if (!attr_done) {
        cudaFuncSetAttribute(proj_kernel,  cudaFuncAttributeMaxDynamicSharedMemorySize, SMEM_BYTES);
        cudaFuncSetAttribute(score_kernel, cudaFuncAttributeMaxDynamicSharedMemorySize, SMEM_BYTES);
        cudaFuncSetAttribute(av_kernel,    cudaFuncAttributeMaxDynamicSharedMemorySize, SMEM_BYTES);
        cudaFuncSetAttribute(up_kernel,    cudaFuncAttributeMaxDynamicSharedMemorySize, SMEM_BYTES);
        attr_done = true;
    }

    long long xp_total = (long long)BATCH * CIN * XPC;
    xpad_kernel<<<(unsigned)((xp_total + 255) / 256), 256>>>(x);
    pb_kernel<<<3 * NTOK * KD / 256, 256>>>(q_w, q_b, k_w, k_b, v_w, v_b);
    wt_kernel<<<3 * 256 * 1024 / 256, 256>>>(q_w, k_w, v_w);
    upwt_kernel<<<1024 * KD / 256, 256>>>(up_w);
    proj_kernel<<<dim3(8, 2, BATCH * 3), 256, SMEM_BYTES>>>();
    vt_kernel<<<dim3(32, 8, BATCH), dim3(32, 8)>>>();
    score_kernel<<<dim3(8, 8, BATCH), 256, SMEM_BYTES>>>();
    softmax_kernel<<<BATCH * NTOK, 128>>>();
    av_kernel<<<dim3(8, 2, BATCH), 256, SMEM_BYTES>>>();
    up_kernel<<<dim3(8, 8, BATCH), 256, SMEM_BYTES>>>(x, up_b, out);
}